// round 4
// baseline (speedup 1.0000x reference)
#include <cuda_runtime.h>
#include <math.h>

// ---------------------------------------------------------------------------
// Problem constants (fixed shapes from reference)
// ---------------------------------------------------------------------------
#define B_    32
#define H_    56
#define W_    56
#define C_    192
#define WS_   7
#define SS_   3
#define NH_   6
#define HD    32          // C_/NH_
#define NN    49          // WS_*WS_
#define NWIN  64          // (H_/WS_)*(W_/WS_)
#define NTOK  (B_*H_*W_)  // 100352
#define HID   768         // 4*C_
#define EPSLN 1e-5f

// ---------------------------------------------------------------------------
// One scratch buffer, regions reused across pipeline stages (disjoint
// lifetimes):
//   region X1: [0, NTOK*C)            x + attn branch (pixel layout); live to end
//   region B : [NTOK*C, 2*NTOK*C)     xw (steps 1-2), then attn out (3-4),
//                                      then xn2 (5-6)
//   region CR: [2*NTOK*C, +NTOK*HID)  qkv (steps 2-3), then h (6-7)
// Total: 2*NTOK*C + NTOK*HID floats = 462 MB
// ---------------------------------------------------------------------------
#define OFF_X1 ((size_t)0)
#define OFF_B  ((size_t)NTOK * C_)
#define OFF_CR ((size_t)2 * NTOK * C_)
__device__ float g_scratch[(size_t)2 * NTOK * C_ + (size_t)NTOK * HID];

// ---------------------------------------------------------------------------
// Helpers
// ---------------------------------------------------------------------------
__device__ __forceinline__ float warp_sum(float v) {
#pragma unroll
    for (int o = 16; o > 0; o >>= 1) v += __shfl_xor_sync(0xffffffffu, v, o);
    return v;
}

// window-token index -> pixel-layout linear index base (without channel)
__device__ __forceinline__ size_t wtok_to_pixel(int tok) {
    int b   = tok / (NWIN * NN);
    int r   = tok % (NWIN * NN);
    int w   = r / NN;
    int n   = r % NN;
    int wh  = w >> 3, ww = w & 7;
    int i   = n / WS_, j = n % WS_;
    int hs  = wh * WS_ + i;               // coordinate in shifted image
    int ws  = ww * WS_ + j;
    int ph  = hs + SS_; if (ph >= H_) ph -= H_;  // original-image pixel
    int pw  = ws + SS_; if (pw >= W_) pw -= W_;
    return ((size_t)(b * H_ + ph) * W_ + pw) * C_;
}

// ---------------------------------------------------------------------------
// Kernel 1: LayerNorm (two modes).
//   mode 0: LN1 + cyclic shift (-3,-3) + window partition. Reads x (pixel
//           layout, gathered), writes dst in window layout.
//   mode 1: plain LN (pixel layout src -> dst).
// One block per token, 192 threads = one per channel.
// ---------------------------------------------------------------------------
__global__ __launch_bounds__(C_) void ln_kernel(
    const float* __restrict__ src0,
    float* __restrict__ dst,
    const float* __restrict__ gma,
    const float* __restrict__ bta,
    int mode)
{
    int tok = blockIdx.x;
    int c   = threadIdx.x;
    const float* src = (mode == 0) ? (src0 + wtok_to_pixel(tok))
                                   : (src0 + (size_t)tok * C_);
    float v = src[c];

    __shared__ float ps[6], ps2[6];
    float s  = warp_sum(v);
    float s2 = warp_sum(v * v);
    int lane = c & 31, wid = c >> 5;
    if (lane == 0) { ps[wid] = s; ps2[wid] = s2; }
    __syncthreads();
    if (c == 0) {
        float a = 0.f, b2 = 0.f;
#pragma unroll
        for (int k = 0; k < 6; k++) { a += ps[k]; b2 += ps2[k]; }
        float mean = a * (1.0f / C_);
        float var  = b2 * (1.0f / C_) - mean * mean;
        ps[0]  = mean;
        ps2[0] = rsqrtf(var + EPSLN);
    }
    __syncthreads();
    float mean = ps[0], rstd = ps2[0];
    dst[(size_t)tok * C_ + c] = (v - mean) * rstd * gma[c] + bta[c];
}

// ---------------------------------------------------------------------------
// Kernel 2: generic tiled fp32 GEMM  C = A[M,K] @ W[K,N] + bias
// 64x64 tile, TK=16, 256 threads, 4x4 register tile per thread.
// act: 0 = none, 1 = exact GELU, 2 = scatter mode (un-window + un-shift the
// row index, add residual res (pixel layout), write to Cc at pixel index).
// res: optional residual added last (act 0/2).
// All M,N,K used here are multiples of 64/64/16 — no bounds checks.
// ---------------------------------------------------------------------------
#define TM 64
#define TN 64
#define TK 16

__global__ __launch_bounds__(256) void gemm_kernel(
    const float* __restrict__ A,
    const float* __restrict__ Wm,
    const float* __restrict__ bias,
    float* __restrict__ Cc,
    int M, int N, int K,
    const float* __restrict__ res,
    int act)
{
    __shared__ float As[TK][TM];  // A tile transposed: As[k][m]
    __shared__ float Bs[TK][TN];

    int tid = threadIdx.x;
    int tx  = tid & 15;           // 0..15 -> 4 cols each
    int ty  = tid >> 4;           // 0..15 -> 4 rows each
    int rowBase = blockIdx.y * TM;
    int colBase = blockIdx.x * TN;

    int arow = tid >> 2;          // 0..63
    int ak   = (tid & 3) * 4;     // 0,4,8,12
    int bk   = tid >> 4;          // 0..15
    int bcol = (tid & 15) * 4;    // 0..60

    float acc[4][4] = {};

    for (int k0 = 0; k0 < K; k0 += TK) {
        float4 av = *(const float4*)(A + (size_t)(rowBase + arow) * K + k0 + ak);
        As[ak + 0][arow] = av.x;
        As[ak + 1][arow] = av.y;
        As[ak + 2][arow] = av.z;
        As[ak + 3][arow] = av.w;
        float4 bv = *(const float4*)(Wm + (size_t)(k0 + bk) * N + colBase + bcol);
        *(float4*)&Bs[bk][bcol] = bv;
        __syncthreads();

#pragma unroll
        for (int k = 0; k < TK; k++) {
            float4 a = *(const float4*)&As[k][ty * 4];
            float4 b = *(const float4*)&Bs[k][tx * 4];
            acc[0][0] += a.x * b.x; acc[0][1] += a.x * b.y; acc[0][2] += a.x * b.z; acc[0][3] += a.x * b.w;
            acc[1][0] += a.y * b.x; acc[1][1] += a.y * b.y; acc[1][2] += a.y * b.z; acc[1][3] += a.y * b.w;
            acc[2][0] += a.z * b.x; acc[2][1] += a.z * b.y; acc[2][2] += a.z * b.z; acc[2][3] += a.z * b.w;
            acc[3][0] += a.w * b.x; acc[3][1] += a.w * b.y; acc[3][2] += a.w * b.z; acc[3][3] += a.w * b.w;
        }
        __syncthreads();
    }

    float4 bv = *(const float4*)(bias + colBase + tx * 4);
    float bb[4] = { bv.x, bv.y, bv.z, bv.w };

#pragma unroll
    for (int i = 0; i < 4; i++) {
        int row = rowBase + ty * 4 + i;
        float v0 = acc[i][0] + bb[0];
        float v1 = acc[i][1] + bb[1];
        float v2 = acc[i][2] + bb[2];
        float v3 = acc[i][3] + bb[3];

        if (act == 2) {
            // scatter: row is a window-token; write at pixel-layout index,
            // adding residual x (pixel layout).
            size_t pbase = wtok_to_pixel(row) + colBase + tx * 4;
            float4 rv = *(const float4*)(res + pbase);
            float4 o;
            o.x = v0 + rv.x; o.y = v1 + rv.y; o.z = v2 + rv.z; o.w = v3 + rv.w;
            *(float4*)(Cc + pbase) = o;
            continue;
        }

        size_t off = (size_t)row * N + colBase + tx * 4;
        if (act == 1) {
            v0 = 0.5f * v0 * (1.0f + erff(v0 * 0.70710678118654752f));
            v1 = 0.5f * v1 * (1.0f + erff(v1 * 0.70710678118654752f));
            v2 = 0.5f * v2 * (1.0f + erff(v2 * 0.70710678118654752f));
            v3 = 0.5f * v3 * (1.0f + erff(v3 * 0.70710678118654752f));
        }
        if (res) {
            float4 rv = *(const float4*)(res + off);
            v0 += rv.x; v1 += rv.y; v2 += rv.z; v3 += rv.w;
        }
        float4 o;
        o.x = v0; o.y = v1; o.z = v2; o.w = v3;
        *(float4*)(Cc + off) = o;
    }
}

// ---------------------------------------------------------------------------
// Kernel 3: windowed attention. One block per (b*window, head), 64 threads.
// Threads 0..48 each own one query row. rel-pos bias + shift mask computed
// analytically.
// ---------------------------------------------------------------------------
__global__ __launch_bounds__(64) void attn_kernel(
    const float* __restrict__ qkv,
    float* __restrict__ attn_out,
    const float* __restrict__ rpb)
{
    int bw   = blockIdx.x;           // b*NWIN + w
    int head = blockIdx.y;           // 0..5
    int w    = bw & (NWIN - 1);
    int wh   = w >> 3, ww = w & 7;

    __shared__ float qs[NN][HD];
    __shared__ float ks[NN][HD];
    __shared__ float vs[NN][HD];
    __shared__ int   lab[NN];

    int tid = threadIdx.x;
    size_t base = (size_t)bw * NN;

    for (int idx = tid; idx < NN * HD; idx += 64) {
        int n = idx >> 5, d = idx & 31;
        size_t ro = (base + n) * (3 * C_) + head * HD + d;
        qs[n][d] = qkv[ro];
        ks[n][d] = qkv[ro + C_];
        vs[n][d] = qkv[ro + 2 * C_];
    }
    if (tid < NN) {
        int i = tid / WS_, j = tid % WS_;
        int hs = wh * WS_ + i, wsx = ww * WS_ + j;
        int rh = hs  < 49 ? 0 : (hs  < 53 ? 1 : 2);
        int rw = wsx < 49 ? 0 : (wsx < 53 ? 1 : 2);
        lab[tid] = rh * 3 + rw;
    }
    __syncthreads();

    if (tid < NN) {
        int n  = tid;
        int i1 = n / WS_, j1 = n % WS_;
        int myLab = lab[n];
        const float scale = 0.17677669529663687f; // 1/sqrt(32)

        float qr[HD];
#pragma unroll
        for (int d = 0; d < HD; d++) qr[d] = qs[n][d];

        float p[NN];
        float mx = -1e30f;
#pragma unroll
        for (int m = 0; m < NN; m++) {
            float s0 = 0.f, s1 = 0.f, s2 = 0.f, s3 = 0.f;
#pragma unroll
            for (int d = 0; d < HD; d += 4) {
                s0 += qr[d + 0] * ks[m][d + 0];
                s1 += qr[d + 1] * ks[m][d + 1];
                s2 += qr[d + 2] * ks[m][d + 2];
                s3 += qr[d + 3] * ks[m][d + 3];
            }
            int i2 = m / WS_, j2 = m % WS_;
            float b = rpb[((i1 - i2 + 6) * 13 + (j1 - j2 + 6)) * NH_ + head];
            if (lab[m] != myLab) b -= 100.f;
            float s = (s0 + s1 + s2 + s3) * scale + b;
            p[m] = s;
            mx = fmaxf(mx, s);
        }
        float sum = 0.f;
#pragma unroll
        for (int m = 0; m < NN; m++) {
            float e = __expf(p[m] - mx);
            p[m] = e;
            sum += e;
        }
        float inv = 1.f / sum;

        float* outp = attn_out + (base + n) * C_ + head * HD;
#pragma unroll 1
        for (int d = 0; d < HD; d++) {
            float o0 = 0.f, o1 = 0.f;
#pragma unroll
            for (int m = 0; m < 48; m += 2) {
                o0 += p[m]     * vs[m][d];
                o1 += p[m + 1] * vs[m + 1][d];
            }
            o0 += p[48] * vs[48][d];
            outp[d] = (o0 + o1) * inv;
        }
    }
}

// ---------------------------------------------------------------------------
// Host launcher
// ---------------------------------------------------------------------------
extern "C" void kernel_launch(void* const* d_in, const int* in_sizes, int n_in,
                              void* d_out, int out_size)
{
    const float* x      = (const float*)d_in[0];
    const float* n1g    = (const float*)d_in[1];
    const float* n1b    = (const float*)d_in[2];
    const float* qkv_w  = (const float*)d_in[3];
    const float* qkv_b  = (const float*)d_in[4];
    const float* rpb    = (const float*)d_in[5];
    const float* proj_w = (const float*)d_in[6];
    const float* proj_b = (const float*)d_in[7];
    const float* n2g    = (const float*)d_in[8];
    const float* n2b    = (const float*)d_in[9];
    const float* fc1_w  = (const float*)d_in[10];
    const float* fc1_b  = (const float*)d_in[11];
    const float* fc2_w  = (const float*)d_in[12];
    const float* fc2_b  = (const float*)d_in[13];
    float* out = (float*)d_out;

    float* scratch = nullptr;
    cudaGetSymbolAddress((void**)&scratch, g_scratch);
    float* p_x1 = scratch + OFF_X1;   // residual-1 result (pixel layout)
    float* p_b  = scratch + OFF_B;    // xw -> attn -> xn2
    float* p_cr = scratch + OFF_CR;   // qkv -> h

    const int M = NTOK;

    // 1. LN1 + shift + window partition: x -> p_b (xw)
    ln_kernel<<<NTOK, C_>>>(x, p_b, n1g, n1b, 0);

    // 2. QKV GEMM: [M,192] @ [192,576] -> p_cr (qkv)
    gemm_kernel<<<dim3(3 * C_ / TN, M / TM), 256>>>(
        p_b, qkv_w, qkv_b, p_cr, M, 3 * C_, C_, nullptr, 0);

    // 3. Windowed attention: p_cr (qkv) -> p_b (attn; xw dead)
    attn_kernel<<<dim3(B_ * NWIN, NH_), 64>>>(p_cr, p_b, rpb);

    // 4. Proj GEMM + scatter + residual 1: [M,192] @ [192,192] -> p_x1 (pixel)
    gemm_kernel<<<dim3(C_ / TN, M / TM), 256>>>(
        p_b, proj_w, proj_b, p_x1, M, C_, C_, x, 2);

    // 5. LN2: p_x1 -> p_b (xn2; attn dead)
    ln_kernel<<<NTOK, C_>>>(p_x1, p_b, n2g, n2b, 1);

    // 6. FC1 + GELU: [M,192] @ [192,768] -> p_cr (h; qkv dead)
    gemm_kernel<<<dim3(HID / TN, M / TM), 256>>>(
        p_b, fc1_w, fc1_b, p_cr, M, HID, C_, nullptr, 1);

    // 7. FC2 + residual 2 -> out: [M,768] @ [768,192]
    gemm_kernel<<<dim3(C_ / TN, M / TM), 256>>>(
        p_cr, fc2_w, fc2_b, out, M, C_, HID, p_x1, 0);
}

// round 5
// speedup vs baseline: 2.0296x; 2.0296x over previous
#include <cuda_runtime.h>
#include <math.h>
#include <stdint.h>

// ---------------------------------------------------------------------------
// Problem constants (fixed shapes from reference)
// ---------------------------------------------------------------------------
#define B_    32
#define H_    56
#define W_    56
#define C_    192
#define WS_   7
#define SS_   3
#define NH_   6
#define HD    32          // C_/NH_
#define NN    49          // WS_*WS_
#define NWIN  64          // (H_/WS_)*(W_/WS_)
#define NTOK  (B_*H_*W_)  // 100352
#define HID   768         // 4*C_
#define EPSLN 1e-5f

// ---------------------------------------------------------------------------
// One scratch buffer, regions reused across pipeline stages (disjoint
// lifetimes):
//   region X1: [0, NTOK*C)            x + attn branch (pixel layout)
//   region B : [NTOK*C, 2*NTOK*C)     xw -> attn -> xn2
//   region CR: [2*NTOK*C, +NTOK*HID)  qkv -> h
// ---------------------------------------------------------------------------
#define OFF_X1 ((size_t)0)
#define OFF_B  ((size_t)NTOK * C_)
#define OFF_CR ((size_t)2 * NTOK * C_)
__device__ float g_scratch[(size_t)2 * NTOK * C_ + (size_t)NTOK * HID];

// ---------------------------------------------------------------------------
// Helpers
// ---------------------------------------------------------------------------
__device__ __forceinline__ float warp_sum(float v) {
#pragma unroll
    for (int o = 16; o > 0; o >>= 1) v += __shfl_xor_sync(0xffffffffu, v, o);
    return v;
}

// window-token index -> pixel-layout linear index base (without channel)
__device__ __forceinline__ size_t wtok_to_pixel(int tok) {
    int b   = tok / (NWIN * NN);
    int r   = tok % (NWIN * NN);
    int w   = r / NN;
    int n   = r % NN;
    int wh  = w >> 3, ww = w & 7;
    int i   = n / WS_, j = n % WS_;
    int hs  = wh * WS_ + i;
    int ws  = ww * WS_ + j;
    int ph  = hs + SS_; if (ph >= H_) ph -= H_;
    int pw  = ws + SS_; if (pw >= W_) pw -= W_;
    return ((size_t)(b * H_ + ph) * W_ + pw) * C_;
}

__device__ __forceinline__ uint32_t f2tf32(float x) {
    uint32_t y;
    asm("cvt.rna.tf32.f32 %0, %1;" : "=r"(y) : "f"(x));
    return y;
}

__device__ __forceinline__ void mma_tf32(float* c, const uint32_t* a, const uint32_t* b) {
    asm volatile(
        "mma.sync.aligned.m16n8k8.row.col.f32.tf32.tf32.f32 "
        "{%0,%1,%2,%3}, {%4,%5,%6,%7}, {%8,%9}, {%0,%1,%2,%3};\n"
        : "+f"(c[0]), "+f"(c[1]), "+f"(c[2]), "+f"(c[3])
        : "r"(a[0]), "r"(a[1]), "r"(a[2]), "r"(a[3]), "r"(b[0]), "r"(b[1]));
}

// ---------------------------------------------------------------------------
// Kernel 1: LayerNorm (two modes).
//   mode 0: LN1 + cyclic shift (-3,-3) + window partition (gather at read).
//   mode 1: plain LN (pixel layout src -> dst).
// ---------------------------------------------------------------------------
__global__ __launch_bounds__(C_) void ln_kernel(
    const float* __restrict__ src0,
    float* __restrict__ dst,
    const float* __restrict__ gma,
    const float* __restrict__ bta,
    int mode)
{
    int tok = blockIdx.x;
    int c   = threadIdx.x;
    const float* src = (mode == 0) ? (src0 + wtok_to_pixel(tok))
                                   : (src0 + (size_t)tok * C_);
    float v = src[c];

    __shared__ float ps[6], ps2[6];
    float s  = warp_sum(v);
    float s2 = warp_sum(v * v);
    int lane = c & 31, wid = c >> 5;
    if (lane == 0) { ps[wid] = s; ps2[wid] = s2; }
    __syncthreads();
    if (c == 0) {
        float a = 0.f, b2 = 0.f;
#pragma unroll
        for (int k = 0; k < 6; k++) { a += ps[k]; b2 += ps2[k]; }
        float mean = a * (1.0f / C_);
        float var  = b2 * (1.0f / C_) - mean * mean;
        ps[0]  = mean;
        ps2[0] = rsqrtf(var + EPSLN);
    }
    __syncthreads();
    float mean = ps[0], rstd = ps2[0];
    dst[(size_t)tok * C_ + c] = (v - mean) * rstd * gma[c] + bta[c];
}

// ---------------------------------------------------------------------------
// Kernel 2: tf32 tensor-core GEMM  C = A[M,K] @ W[K,N] + bias
// Block tile 128x64x32, 256 threads = 8 warps (4 along M, 2 along N),
// each warp computes a 32x32 tile via mma.sync.m16n8k8 (2 m-tiles x 4 n-tiles).
// Conflict-free smem: As[128][36] (m-major), Bs[32][68] (k-major).
// act: 0 = none, 1 = exact GELU, 2 = scatter mode (un-window + un-shift row
//      index, add pixel-layout residual, write at pixel index).
// M % 128 == 0, N % 64 == 0, K % 32 == 0 for all call sites.
// ---------------------------------------------------------------------------
#define BM 128
#define BN 64
#define BK 32
#define ASTR 36
#define BSTR 68

__global__ __launch_bounds__(256) void gemm_tc_kernel(
    const float* __restrict__ A,
    const float* __restrict__ Wm,
    const float* __restrict__ bias,
    float* __restrict__ Cc,
    int M, int N, int K,
    const float* __restrict__ res,
    int act)
{
    __shared__ uint32_t As[BM * ASTR];
    __shared__ uint32_t Bs[BK * BSTR];

    int tid  = threadIdx.x;
    int lane = tid & 31;
    int gid  = lane >> 2;     // 0..7
    int tig  = lane & 3;      // 0..3
    int wId  = tid >> 5;      // 0..7
    int wm   = wId & 3;       // warp row  (4 x 32 = 128)
    int wn   = wId >> 2;      // warp col  (2 x 32 = 64)

    int rowBase = blockIdx.y * BM;
    int colBase = blockIdx.x * BN;

    // global-load assignments
    int aRow0 = tid >> 3;          // 0..31, 4 passes of 32 rows
    int aCol4 = (tid & 7) * 4;     // 0..28
    int bRow0 = tid >> 4;          // 0..15, 2 passes of 16 rows
    int bCol4 = (tid & 15) * 4;    // 0..60

    const float* Aptr = A + (size_t)rowBase * K;
    const float* Bptr = Wm + colBase;

    float4 aReg[4];
    float4 bReg[2];

    // prefetch tile 0
#pragma unroll
    for (int p = 0; p < 4; p++)
        aReg[p] = *(const float4*)(Aptr + (size_t)(aRow0 + 32 * p) * K + aCol4);
#pragma unroll
    for (int p = 0; p < 2; p++)
        bReg[p] = *(const float4*)(Bptr + (size_t)(bRow0 + 16 * p) * N + bCol4);

    float acc[2][4][4];
#pragma unroll
    for (int mt = 0; mt < 2; mt++)
#pragma unroll
        for (int nt = 0; nt < 4; nt++)
#pragma unroll
            for (int i = 0; i < 4; i++) acc[mt][nt][i] = 0.f;

    int nIters = K / BK;
    for (int it = 0; it < nIters; ++it) {
        // store prefetched tile to smem (converted to tf32)
#pragma unroll
        for (int p = 0; p < 4; p++) {
            uint4 u;
            u.x = f2tf32(aReg[p].x); u.y = f2tf32(aReg[p].y);
            u.z = f2tf32(aReg[p].z); u.w = f2tf32(aReg[p].w);
            *(uint4*)&As[(aRow0 + 32 * p) * ASTR + aCol4] = u;
        }
#pragma unroll
        for (int p = 0; p < 2; p++) {
            uint4 u;
            u.x = f2tf32(bReg[p].x); u.y = f2tf32(bReg[p].y);
            u.z = f2tf32(bReg[p].z); u.w = f2tf32(bReg[p].w);
            *(uint4*)&Bs[(bRow0 + 16 * p) * BSTR + bCol4] = u;
        }
        __syncthreads();

        // prefetch next tile
        if (it + 1 < nIters) {
            int k0 = (it + 1) * BK;
#pragma unroll
            for (int p = 0; p < 4; p++)
                aReg[p] = *(const float4*)(Aptr + (size_t)(aRow0 + 32 * p) * K + k0 + aCol4);
#pragma unroll
            for (int p = 0; p < 2; p++)
                bReg[p] = *(const float4*)(Bptr + (size_t)(k0 + bRow0 + 16 * p) * N + bCol4);
        }

        // compute 4 k8 steps
#pragma unroll
        for (int k8 = 0; k8 < 4; k8++) {
            int kb = k8 * 8;
            uint32_t af[2][4];
#pragma unroll
            for (int mt = 0; mt < 2; mt++) {
                int r = wm * 32 + mt * 16 + gid;
                af[mt][0] = As[r * ASTR + kb + tig];
                af[mt][1] = As[(r + 8) * ASTR + kb + tig];
                af[mt][2] = As[r * ASTR + kb + tig + 4];
                af[mt][3] = As[(r + 8) * ASTR + kb + tig + 4];
            }
            uint32_t bf[4][2];
#pragma unroll
            for (int nt = 0; nt < 4; nt++) {
                int cidx = wn * 32 + nt * 8 + gid;
                bf[nt][0] = Bs[(kb + tig) * BSTR + cidx];
                bf[nt][1] = Bs[(kb + tig + 4) * BSTR + cidx];
            }
#pragma unroll
            for (int mt = 0; mt < 2; mt++)
#pragma unroll
                for (int nt = 0; nt < 4; nt++)
                    mma_tf32(acc[mt][nt], af[mt], bf[nt]);
        }
        __syncthreads();
    }

    // ---------------- epilogue ----------------
#pragma unroll
    for (int mt = 0; mt < 2; mt++) {
        int row0 = rowBase + wm * 32 + mt * 16 + gid;
        int row1 = row0 + 8;
        size_t p0 = 0, p1 = 0;
        if (act == 2) {
            p0 = wtok_to_pixel(row0);
            p1 = wtok_to_pixel(row1);
        }
#pragma unroll
        for (int nt = 0; nt < 4; nt++) {
            int col = colBase + wn * 32 + nt * 8 + 2 * tig;
            float bb0 = bias[col], bb1 = bias[col + 1];
            float v00 = acc[mt][nt][0] + bb0;
            float v01 = acc[mt][nt][1] + bb1;
            float v10 = acc[mt][nt][2] + bb0;
            float v11 = acc[mt][nt][3] + bb1;

            if (act == 2) {
                float2 r0 = *(const float2*)(res + p0 + col);
                float2 r1 = *(const float2*)(res + p1 + col);
                float2 o0 = { v00 + r0.x, v01 + r0.y };
                float2 o1 = { v10 + r1.x, v11 + r1.y };
                *(float2*)(Cc + p0 + col) = o0;
                *(float2*)(Cc + p1 + col) = o1;
                continue;
            }

            if (act == 1) {
                v00 = 0.5f * v00 * (1.0f + erff(v00 * 0.70710678118654752f));
                v01 = 0.5f * v01 * (1.0f + erff(v01 * 0.70710678118654752f));
                v10 = 0.5f * v10 * (1.0f + erff(v10 * 0.70710678118654752f));
                v11 = 0.5f * v11 * (1.0f + erff(v11 * 0.70710678118654752f));
            }
            size_t off0 = (size_t)row0 * N + col;
            size_t off1 = (size_t)row1 * N + col;
            if (res) {
                float2 r0 = *(const float2*)(res + off0);
                float2 r1 = *(const float2*)(res + off1);
                v00 += r0.x; v01 += r0.y; v10 += r1.x; v11 += r1.y;
            }
            float2 o0 = { v00, v01 };
            float2 o1 = { v10, v11 };
            *(float2*)(Cc + off0) = o0;
            *(float2*)(Cc + off1) = o1;
        }
    }
}

// ---------------------------------------------------------------------------
// Kernel 3: windowed attention. One block per (b*window, head), 64 threads.
// ---------------------------------------------------------------------------
__global__ __launch_bounds__(64) void attn_kernel(
    const float* __restrict__ qkv,
    float* __restrict__ attn_out,
    const float* __restrict__ rpb)
{
    int bw   = blockIdx.x;           // b*NWIN + w
    int head = blockIdx.y;           // 0..5
    int w    = bw & (NWIN - 1);
    int wh   = w >> 3, ww = w & 7;

    __shared__ float qs[NN][HD];
    __shared__ float ks[NN][HD];
    __shared__ float vs[NN][HD];
    __shared__ int   lab[NN];

    int tid = threadIdx.x;
    size_t base = (size_t)bw * NN;

    for (int idx = tid; idx < NN * HD; idx += 64) {
        int n = idx >> 5, d = idx & 31;
        size_t ro = (base + n) * (3 * C_) + head * HD + d;
        qs[n][d] = qkv[ro];
        ks[n][d] = qkv[ro + C_];
        vs[n][d] = qkv[ro + 2 * C_];
    }
    if (tid < NN) {
        int i = tid / WS_, j = tid % WS_;
        int hs = wh * WS_ + i, wsx = ww * WS_ + j;
        int rh = hs  < 49 ? 0 : (hs  < 53 ? 1 : 2);
        int rw = wsx < 49 ? 0 : (wsx < 53 ? 1 : 2);
        lab[tid] = rh * 3 + rw;
    }
    __syncthreads();

    if (tid < NN) {
        int n  = tid;
        int i1 = n / WS_, j1 = n % WS_;
        int myLab = lab[n];
        const float scale = 0.17677669529663687f; // 1/sqrt(32)

        float qr[HD];
#pragma unroll
        for (int d = 0; d < HD; d++) qr[d] = qs[n][d];

        float p[NN];
        float mx = -1e30f;
#pragma unroll
        for (int m = 0; m < NN; m++) {
            float s0 = 0.f, s1 = 0.f, s2 = 0.f, s3 = 0.f;
#pragma unroll
            for (int d = 0; d < HD; d += 4) {
                s0 += qr[d + 0] * ks[m][d + 0];
                s1 += qr[d + 1] * ks[m][d + 1];
                s2 += qr[d + 2] * ks[m][d + 2];
                s3 += qr[d + 3] * ks[m][d + 3];
            }
            int i2 = m / WS_, j2 = m % WS_;
            float b = rpb[((i1 - i2 + 6) * 13 + (j1 - j2 + 6)) * NH_ + head];
            if (lab[m] != myLab) b -= 100.f;
            float s = (s0 + s1 + s2 + s3) * scale + b;
            p[m] = s;
            mx = fmaxf(mx, s);
        }
        float sum = 0.f;
#pragma unroll
        for (int m = 0; m < NN; m++) {
            float e = __expf(p[m] - mx);
            p[m] = e;
            sum += e;
        }
        float inv = 1.f / sum;

        float* outp = attn_out + (base + n) * C_ + head * HD;
#pragma unroll 1
        for (int d = 0; d < HD; d++) {
            float o0 = 0.f, o1 = 0.f;
#pragma unroll
            for (int m = 0; m < 48; m += 2) {
                o0 += p[m]     * vs[m][d];
                o1 += p[m + 1] * vs[m + 1][d];
            }
            o0 += p[48] * vs[48][d];
            outp[d] = (o0 + o1) * inv;
        }
    }
}

// ---------------------------------------------------------------------------
// Host launcher
// ---------------------------------------------------------------------------
extern "C" void kernel_launch(void* const* d_in, const int* in_sizes, int n_in,
                              void* d_out, int out_size)
{
    const float* x      = (const float*)d_in[0];
    const float* n1g    = (const float*)d_in[1];
    const float* n1b    = (const float*)d_in[2];
    const float* qkv_w  = (const float*)d_in[3];
    const float* qkv_b  = (const float*)d_in[4];
    const float* rpb    = (const float*)d_in[5];
    const float* proj_w = (const float*)d_in[6];
    const float* proj_b = (const float*)d_in[7];
    const float* n2g    = (const float*)d_in[8];
    const float* n2b    = (const float*)d_in[9];
    const float* fc1_w  = (const float*)d_in[10];
    const float* fc1_b  = (const float*)d_in[11];
    const float* fc2_w  = (const float*)d_in[12];
    const float* fc2_b  = (const float*)d_in[13];
    float* out = (float*)d_out;

    float* scratch = nullptr;
    cudaGetSymbolAddress((void**)&scratch, g_scratch);
    float* p_x1 = scratch + OFF_X1;   // residual-1 result (pixel layout)
    float* p_b  = scratch + OFF_B;    // xw -> attn -> xn2
    float* p_cr = scratch + OFF_CR;   // qkv -> h

    const int M = NTOK;

    // 1. LN1 + shift + window partition: x -> p_b (xw)
    ln_kernel<<<NTOK, C_>>>(x, p_b, n1g, n1b, 0);

    // 2. QKV GEMM: [M,192] @ [192,576] -> p_cr (qkv)
    gemm_tc_kernel<<<dim3(3 * C_ / BN, M / BM), 256>>>(
        p_b, qkv_w, qkv_b, p_cr, M, 3 * C_, C_, nullptr, 0);

    // 3. Windowed attention: p_cr (qkv) -> p_b (attn; xw dead)
    attn_kernel<<<dim3(B_ * NWIN, NH_), 64>>>(p_cr, p_b, rpb);

    // 4. Proj GEMM + scatter + residual 1: [M,192] @ [192,192] -> p_x1 (pixel)
    gemm_tc_kernel<<<dim3(C_ / BN, M / BM), 256>>>(
        p_b, proj_w, proj_b, p_x1, M, C_, C_, x, 2);

    // 5. LN2: p_x1 -> p_b (xn2; attn dead)
    ln_kernel<<<NTOK, C_>>>(p_x1, p_b, n2g, n2b, 1);

    // 6. FC1 + GELU: [M,192] @ [192,768] -> p_cr (h; qkv dead)
    gemm_tc_kernel<<<dim3(HID / BN, M / BM), 256>>>(
        p_b, fc1_w, fc1_b, p_cr, M, HID, C_, nullptr, 1);

    // 7. FC2 + residual 2 -> out: [M,768] @ [768,192]
    gemm_tc_kernel<<<dim3(C_ / BN, M / BM), 256>>>(
        p_cr, fc2_w, fc2_b, out, M, C_, HID, p_x1, 0);
}